// round 13
// baseline (speedup 1.0000x reference)
#include <cuda_runtime.h>

#define N_FFT    800
#define HOP      200
#define BATCH    32
#define TLEN     480000
#define PAD      400
#define N_FRAMES 2401                 // frames per batch
#define NHOP     2404                 // hop blocks per batch: 480800/200
#define AOUT     120                  // C outputs (q positions) per A-block
#define AHOPS    (AOUT + 6)           // computed hop sums incl. 3+3 halo (126)
#define ATHR     512                  // 504 active (4/hop), 8 converged dummies
#define NQUAD    (TLEN / 4)           // 120000 output quads per batch

#define PI_D 3.14159265358979323846

// Fully fused STFT->mag/phase->iSTFT (linear-collapse derivation, R3/R6):
//   Hann identities: win(r+400)=1-win(r), win(r+600)=1-win(r+200),
//   sum_j win(r+200j)^2 = 1.5 exactly.
//   Per hop block g: X=sum(x), A=sum(win(r)x), B=sum(win(r+200)x) (per parity).
//   S[f] = A[f] + B[f+1] + (X[f+2]-A[f+2]) + (X[f+3]-B[f+3]);  S=0 off-range.
//   out = 0.75*x + (C0 + win(r)*C1 + win(r+200)*C2)/800,
//     C0=S[q-2]+S[q-3], C1=S[q]-S[q-2], C2=S[q-1]-S[q-3]  (per parity).
//   Missing frame j at signal edge additionally: out -= 0.5*x*win(r+200j)^2.
//
// Two-kernel split: A computes C combos into global scratch; B is a pure
// stream: x (L2-warm LDG) + C (broadcast LDG) + window (LDS) -> out (STG.cs).

__device__ float gC[BATCH][NHOP][8];   // {C0e,C0o,C1e,C1o,C2e,C2o,0,0}

// ---------------- Kernel A: hop sums + C combos ----------------
__global__ __launch_bounds__(ATHR, 4)
void sums_kernel(const float* __restrict__ x) {
    __shared__ __align__(16) float sw[400];       // win[0..400)
    __shared__ float sXAB[AHOPS][6];              // {Xe,Xo,Ae,Ao,Be,Bo}

    const int b   = blockIdx.y;
    const int Q0  = blockIdx.x * AOUT;
    const int tid = threadIdx.x;
    const float* __restrict__ xb = x + (size_t)b * TLEN;

    for (int i = tid; i < 400; i += ATHR)
        sw[i] = 0.5f - 0.5f * __cosf((float)i * (float)(2.0 * PI_D / N_FFT));
    __syncthreads();

    // 4 threads per hop block; groups >= AHOPS are converged dummies.
    const int grp = tid >> 2;
    const int j   = tid & 3;
    const int gh  = Q0 - 3 + (grp < AHOPS ? grp : AHOPS - 1);
    const float4* __restrict__ sw4 = (const float4*)sw;

    float xe = 0.f, xo = 0.f, ae = 0.f, ao = 0.f, be = 0.f, bo = 0.f;
    if (gh >= 2 && gh <= 2401) {
        // Interior: xp[200*gh + r] = x[200*gh + r - 400], all in range.
        const float4* __restrict__ xs = (const float4*)xb + (50 * gh - 100);
        #pragma unroll
        for (int k = 0; k < 13; k++) {
            const int c = j + 4 * k;
            if (c < 50) {
                const float4 v  = xs[c];
                const float4 wa = sw4[c];
                const float4 wb = sw4[c + 50];
                xe += v.x + v.z;                   xo += v.y + v.w;
                ae = fmaf(wa.x, v.x, fmaf(wa.z, v.z, ae));
                ao = fmaf(wa.y, v.y, fmaf(wa.w, v.w, ao));
                be = fmaf(wb.x, v.x, fmaf(wb.z, v.z, be));
                bo = fmaf(wb.y, v.y, fmaf(wb.w, v.w, bo));
            }
        }
    } else {
        // Edge hop blocks (0,1,2402,2403 + halo dummies): clamped scalar.
        #pragma unroll
        for (int k = 0; k < 13; k++) {
            const int c = j + 4 * k;
            if (c < 50) {
                const int r = 4 * c;
                #pragma unroll
                for (int e = 0; e < 4; e += 2) {
                    int p0 = 200 * gh + r + e - PAD;        // even element
                    int p1 = p0 + 1;                        // odd element
                    p0 = p0 < 0 ? 0 : (p0 >= TLEN ? TLEN - 1 : p0);
                    p1 = p1 < 0 ? 0 : (p1 >= TLEN ? TLEN - 1 : p1);
                    const float v0 = xb[p0], v1 = xb[p1];
                    xe += v0;                         xo += v1;
                    ae = fmaf(sw[r + e], v0, ae);     ao = fmaf(sw[r + e + 1], v1, ao);
                    be = fmaf(sw[r + e + 200], v0, be);
                    bo = fmaf(sw[r + e + 201], v1, bo);
                }
            }
        }
    }
    #pragma unroll
    for (int d = 1; d <= 2; d <<= 1) {
        xe += __shfl_xor_sync(0xffffffffu, xe, d);
        xo += __shfl_xor_sync(0xffffffffu, xo, d);
        ae += __shfl_xor_sync(0xffffffffu, ae, d);
        ao += __shfl_xor_sync(0xffffffffu, ao, d);
        be += __shfl_xor_sync(0xffffffffu, be, d);
        bo += __shfl_xor_sync(0xffffffffu, bo, d);
    }
    if (j == 0 && grp < AHOPS) {
        sXAB[grp][0] = xe; sXAB[grp][1] = xo;
        sXAB[grp][2] = ae; sXAB[grp][3] = ao;
        sXAB[grp][4] = be; sXAB[grp][5] = bo;
    }
    __syncthreads();

    // C combos for q = Q0 + ql, per parity. Invalid frames -> S = 0.
    if (tid < 2 * AOUT) {
        const int ql = tid >> 1, par = tid & 1;
        const int q  = Q0 + ql;
        if (q < NHOP) {
            float s[4];                           // s[jj] = S(q - jj)
            #pragma unroll
            for (int jj = 0; jj < 4; jj++) {
                const int f  = q - jj;
                const int fl = ql + 3 - jj;       // hop f local index
                const float v = sXAB[fl][2 + par] + sXAB[fl + 1][4 + par]
                              + (sXAB[fl + 2][par] - sXAB[fl + 2][2 + par])
                              + (sXAB[fl + 3][par] - sXAB[fl + 3][4 + par]);
                s[jj] = (f < 0 || f >= N_FRAMES) ? 0.0f : v;
            }
            float* __restrict__ cp = gC[b][q];
            cp[0 + par] = s[2] + s[3];            // C0
            cp[2 + par] = s[0] - s[2];            // C1
            cp[4 + par] = s[1] - s[3];            // C2
        }
    }
}

// ---------------- Kernel B: streaming synthesis ----------------
__global__ __launch_bounds__(256, 8)
void synth_kernel(const float* __restrict__ x, float* __restrict__ out) {
    __shared__ __align__(16) float sw[N_FFT];

    const int b   = blockIdx.y;
    const int tid = threadIdx.x;
    for (int i = tid; i < N_FFT; i += 256)
        sw[i] = 0.5f - 0.5f * __cosf((float)i * (float)(2.0 * PI_D / N_FFT));
    __syncthreads();

    const float4* __restrict__ sw4 = (const float4*)sw;
    const float4* __restrict__ x4  = (const float4*)(x + (size_t)b * TLEN);
    float4* __restrict__ o4        = (float4*)(out + (size_t)b * TLEN);
    const float* __restrict__ cbase = &gC[b][0][0];
    const int V0 = blockIdx.x * 1024;

    #pragma unroll
    for (int k = 0; k < 4; k++) {
        const int v = V0 + tid + 256 * k;
        if (v < NQUAD) {
            const int u  = v + 100;               // (4v + PAD)/4
            const int q  = u / 50;                // frame position
            const int r4 = u - 50 * q;            // r = 4*r4
            const float4 xv = __ldg(&x4[v]);
            const float4 w0 = sw4[r4];
            const float4 w1 = sw4[r4 + 50];
            const float* __restrict__ cp = cbase + 8 * q;
            const float4 cA = *(const float4*)cp;        // C0e,C0o,C1e,C1o
            const float4 cB = *(const float4*)(cp + 4);  // C2e,C2o,0,0
            float4 o;   // parities: x,z even; y,w odd
            o.x = fmaf(0.75f, xv.x, fmaf(w1.x, cB.x, fmaf(w0.x, cA.z, cA.x)) * (1.0f / 800.0f));
            o.y = fmaf(0.75f, xv.y, fmaf(w1.y, cB.y, fmaf(w0.y, cA.w, cA.y)) * (1.0f / 800.0f));
            o.z = fmaf(0.75f, xv.z, fmaf(w1.z, cB.x, fmaf(w0.z, cA.z, cA.x)) * (1.0f / 800.0f));
            o.w = fmaf(0.75f, xv.w, fmaf(w1.w, cB.y, fmaf(w0.w, cA.w, cA.y)) * (1.0f / 800.0f));
            // Edge wsq corrections (first/last 50 quads of each batch).
            if (v < 50) {                         // missing frame j=3 (win r+600)
                const float4 w3 = sw4[r4 + 150];
                o.x = fmaf(-0.5f * w3.x * w3.x, xv.x, o.x);
                o.y = fmaf(-0.5f * w3.y * w3.y, xv.y, o.y);
                o.z = fmaf(-0.5f * w3.z * w3.z, xv.z, o.z);
                o.w = fmaf(-0.5f * w3.w * w3.w, xv.w, o.w);
            }
            if (v >= NQUAD - 50) {                // missing frame j=0 (win r)
                o.x = fmaf(-0.5f * w0.x * w0.x, xv.x, o.x);
                o.y = fmaf(-0.5f * w0.y * w0.y, xv.y, o.y);
                o.z = fmaf(-0.5f * w0.z * w0.z, xv.z, o.z);
                o.w = fmaf(-0.5f * w0.w * w0.w, xv.w, o.w);
            }
            __stcs(&o4[v], o);                    // streaming store: don't
        }                                         // pollute L2 (write-once)
    }
}

extern "C" void kernel_launch(void* const* d_in, const int* in_sizes, int n_in,
                              void* d_out, int out_size) {
    const float* x = (const float*)d_in[0];
    float* out = (float*)d_out;

    dim3 gridA((NHOP + AOUT - 1) / AOUT, BATCH);      // 21 x 32
    sums_kernel<<<gridA, ATHR>>>(x);

    dim3 gridB((NQUAD + 1023) / 1024, BATCH);         // 118 x 32
    synth_kernel<<<gridB, 256>>>(x, out);
}

// round 14
// speedup vs baseline: 1.1308x; 1.1308x over previous
#include <cuda_runtime.h>

#define N_FFT    800
#define HOP      200
#define BATCH    32
#define TLEN     480000
#define PAD      400
#define N_FRAMES 2401                 // frames per batch
#define NHOP     2404                 // hop blocks per batch: 480800/200
#define AOUT     58                   // C outputs (q positions) per A-block
#define AHOPS    64                   // hop sums per block incl. 3+3 halo
#define NQUAD    (TLEN / 4)           // 120000 output quads per batch
#define BGRID    37                   // B: x-grid; 37*32 = 1184 = 148 SMs * 8

#define PI_D 3.14159265358979323846

// Fully fused STFT->mag/phase->iSTFT (linear-collapse derivation, R3/R6):
//   Hann identities: win(r+400)=1-win(r), win(r+600)=1-win(r+200),
//   sum_j win(r+200j)^2 = 1.5 exactly.
//   Per hop block g: X=sum(x), A=sum(win(r)x), B=sum(win(r+200)x) (per parity).
//   S[f] = A[f] + B[f+1] + (X[f+2]-A[f+2]) + (X[f+3]-B[f+3]);  S=0 off-range.
//   out = 0.75*x + (C0 + win(r)*C1 + win(r+200)*C2)/800,
//     C0=S[q-2]+S[q-3], C1=S[q]-S[q-2], C2=S[q-1]-S[q-3]  (per parity).
//   Missing frame j at signal edge additionally: out -= 0.5*x*win(r+200j)^2.

__device__ float gC[BATCH][NHOP][8];   // {C0e,C0o,C1e,C1o,C2e,C2o,0,0}

// ---------------- Kernel A: hop sums + C combos ----------------
// 256 threads, ALL active: 4 threads per hop block x 64 hop blocks.
__global__ __launch_bounds__(256, 8)
void sums_kernel(const float* __restrict__ x) {
    __shared__ __align__(16) float sw[400];       // win[0..400)
    __shared__ float sXAB[AHOPS][6];              // {Xe,Xo,Ae,Ao,Be,Bo}

    const int b   = blockIdx.y;
    const int Q0  = blockIdx.x * AOUT;
    const int tid = threadIdx.x;
    const float* __restrict__ xb = x + (size_t)b * TLEN;

    for (int i = tid; i < 400; i += 256)
        sw[i] = 0.5f - 0.5f * __cosf((float)i * (float)(2.0 * PI_D / N_FFT));
    __syncthreads();

    const int grp = tid >> 2;                     // 0..63
    const int j   = tid & 3;
    const int gh  = Q0 - 3 + grp;                 // hop index (may be off-range)
    const float4* __restrict__ sw4 = (const float4*)sw;

    float xe = 0.f, xo = 0.f, ae = 0.f, ao = 0.f, be = 0.f, bo = 0.f;
    if (gh >= 2 && gh <= 2401) {
        // Interior: xp[200*gh + r] = x[200*gh + r - 400], all in range.
        const float4* __restrict__ xs = (const float4*)xb + (50 * gh - 100);
        #pragma unroll
        for (int k = 0; k < 13; k++) {
            const int c = j + 4 * k;
            if (c < 50) {
                const float4 v  = __ldg(&xs[c]);
                const float4 wa = sw4[c];
                const float4 wb = sw4[c + 50];
                xe += v.x + v.z;                   xo += v.y + v.w;
                ae = fmaf(wa.x, v.x, fmaf(wa.z, v.z, ae));
                ao = fmaf(wa.y, v.y, fmaf(wa.w, v.w, ao));
                be = fmaf(wb.x, v.x, fmaf(wb.z, v.z, be));
                bo = fmaf(wb.y, v.y, fmaf(wb.w, v.w, bo));
            }
        }
    } else {
        // Edge/off-range hop blocks: clamped scalar path (always in-bounds).
        #pragma unroll
        for (int k = 0; k < 13; k++) {
            const int c = j + 4 * k;
            if (c < 50) {
                const int r = 4 * c;
                #pragma unroll
                for (int e = 0; e < 4; e += 2) {
                    int p0 = 200 * gh + r + e - PAD;        // even element
                    int p1 = p0 + 1;                        // odd element
                    p0 = p0 < 0 ? 0 : (p0 >= TLEN ? TLEN - 1 : p0);
                    p1 = p1 < 0 ? 0 : (p1 >= TLEN ? TLEN - 1 : p1);
                    const float v0 = xb[p0], v1 = xb[p1];
                    xe += v0;                         xo += v1;
                    ae = fmaf(sw[r + e], v0, ae);     ao = fmaf(sw[r + e + 1], v1, ao);
                    be = fmaf(sw[r + e + 200], v0, be);
                    bo = fmaf(sw[r + e + 201], v1, bo);
                }
            }
        }
    }
    #pragma unroll
    for (int d = 1; d <= 2; d <<= 1) {
        xe += __shfl_xor_sync(0xffffffffu, xe, d);
        xo += __shfl_xor_sync(0xffffffffu, xo, d);
        ae += __shfl_xor_sync(0xffffffffu, ae, d);
        ao += __shfl_xor_sync(0xffffffffu, ao, d);
        be += __shfl_xor_sync(0xffffffffu, be, d);
        bo += __shfl_xor_sync(0xffffffffu, bo, d);
    }
    if (j == 0) {
        sXAB[grp][0] = xe; sXAB[grp][1] = xo;
        sXAB[grp][2] = ae; sXAB[grp][3] = ao;
        sXAB[grp][4] = be; sXAB[grp][5] = bo;
    }
    __syncthreads();

    // C combos for q = Q0 + ql, per parity. Invalid frames -> S = 0.
    if (tid < 2 * AOUT) {
        const int ql = tid >> 1, par = tid & 1;   // ql in [0,58)
        const int q  = Q0 + ql;
        if (q < NHOP) {
            float s[4];                           // s[jj] = S(q - jj)
            #pragma unroll
            for (int jj = 0; jj < 4; jj++) {
                const int f  = q - jj;
                const int fl = ql + 3 - jj;       // 0..60; fl+3 <= 63
                const float v = sXAB[fl][2 + par] + sXAB[fl + 1][4 + par]
                              + (sXAB[fl + 2][par] - sXAB[fl + 2][2 + par])
                              + (sXAB[fl + 3][par] - sXAB[fl + 3][4 + par]);
                s[jj] = (f < 0 || f >= N_FRAMES) ? 0.0f : v;
            }
            float* __restrict__ cp = gC[b][q];
            cp[0 + par] = s[2] + s[3];            // C0
            cp[2 + par] = s[0] - s[2];            // C1
            cp[4 + par] = s[1] - s[3];            // C2
        }
    }
}

// ---------------- Kernel B: single-wave streaming synthesis ----------------
// Grid exactly fills the chip (1184 blocks @ occ 8); each block strides over
// 256-quad groups -> no wave quantization, sw init amortized ~13x.
__global__ __launch_bounds__(256, 8)
void synth_kernel(const float* __restrict__ x, float* __restrict__ out) {
    __shared__ __align__(16) float sw[N_FFT];

    const int b   = blockIdx.y;
    const int tid = threadIdx.x;
    for (int i = tid; i < N_FFT; i += 256)
        sw[i] = 0.5f - 0.5f * __cosf((float)i * (float)(2.0 * PI_D / N_FFT));
    __syncthreads();

    const float4* __restrict__ sw4 = (const float4*)sw;
    const float4* __restrict__ x4  = (const float4*)(x + (size_t)b * TLEN);
    float4* __restrict__ o4        = (float4*)(out + (size_t)b * TLEN);
    const float* __restrict__ cbase = &gC[b][0][0];

    #pragma unroll 2
    for (int v = blockIdx.x * 256 + tid; v < NQUAD; v += BGRID * 256) {
        const int u  = v + 100;                   // (4v + PAD)/4
        const int q  = u / 50;                    // frame position
        const int r4 = u - 50 * q;                // r = 4*r4
        const float4 xv = __ldg(&x4[v]);
        const float4 w0 = sw4[r4];
        const float4 w1 = sw4[r4 + 50];
        const float* __restrict__ cp = cbase + 8 * q;
        const float4 cA = *(const float4*)cp;        // C0e,C0o,C1e,C1o
        const float4 cB = *(const float4*)(cp + 4);  // C2e,C2o,0,0
        float4 o;   // parities: x,z even; y,w odd
        o.x = fmaf(0.75f, xv.x, fmaf(w1.x, cB.x, fmaf(w0.x, cA.z, cA.x)) * (1.0f / 800.0f));
        o.y = fmaf(0.75f, xv.y, fmaf(w1.y, cB.y, fmaf(w0.y, cA.w, cA.y)) * (1.0f / 800.0f));
        o.z = fmaf(0.75f, xv.z, fmaf(w1.z, cB.x, fmaf(w0.z, cA.z, cA.x)) * (1.0f / 800.0f));
        o.w = fmaf(0.75f, xv.w, fmaf(w1.w, cB.y, fmaf(w0.w, cA.w, cA.y)) * (1.0f / 800.0f));
        // Edge wsq corrections (first/last 50 quads of each batch only).
        if (v < 50) {                             // missing frame j=3 (win r+600)
            const float4 w3 = sw4[r4 + 150];
            o.x = fmaf(-0.5f * w3.x * w3.x, xv.x, o.x);
            o.y = fmaf(-0.5f * w3.y * w3.y, xv.y, o.y);
            o.z = fmaf(-0.5f * w3.z * w3.z, xv.z, o.z);
            o.w = fmaf(-0.5f * w3.w * w3.w, xv.w, o.w);
        }
        if (v >= NQUAD - 50) {                    // missing frame j=0 (win r)
            o.x = fmaf(-0.5f * w0.x * w0.x, xv.x, o.x);
            o.y = fmaf(-0.5f * w0.y * w0.y, xv.y, o.y);
            o.z = fmaf(-0.5f * w0.z * w0.z, xv.z, o.z);
            o.w = fmaf(-0.5f * w0.w * w0.w, xv.w, o.w);
        }
        __stcs(&o4[v], o);                        // streaming store (write-once)
    }
}

extern "C" void kernel_launch(void* const* d_in, const int* in_sizes, int n_in,
                              void* d_out, int out_size) {
    const float* x = (const float*)d_in[0];
    float* out = (float*)d_out;

    dim3 gridA((NHOP + AOUT - 1) / AOUT, BATCH);      // 42 x 32 = 1344 blocks
    sums_kernel<<<gridA, 256>>>(x);

    dim3 gridB(BGRID, BATCH);                         // 37 x 32 = 1184 blocks
    synth_kernel<<<gridB, 256>>>(x, out);
}